// round 6
// baseline (speedup 1.0000x reference)
#include <cuda_runtime.h>
#include <stdint.h>

// ---------------------------------------------------------------------------
// HistogramQuantizer R6 — 2 kernels, L2 inter-kernel reuse:
//   pass1: FORWARD stream with DEFAULT caching (L2 retains the tail of x),
//          exact max|x| (FMNMX tree, compute-bound floor ~1 op/elem) +
//          4096-bin sampled histogram (1/32, shared-privatized).
//   quant: block 0 does the parallel percentile scan (EMA buffer -> d_out[n],
//          re-zeroes g_hist); all blocks then stream x->out in REVERSE order
//          so the L2-resident tail of x from pass1 is consumed as hits before
//          being evicted. Stores use __stcs (evict-first) to protect the hot
//          read region. Last block self-cleans g_maxbits/g_ctr.
// ---------------------------------------------------------------------------

#define NBINS 4096
#define P1_THREADS 256
#define P1_BLOCKS 1184   // 148 SMs * 8 ; stride multiple of 8
#define Q_THREADS 256
#define Q_BLOCKS 2368    // 148 SMs * 16

__device__ unsigned int g_hist[NBINS];    // zero at module load; scan re-zeroes
__device__ unsigned int g_maxbits;        // reset by last quant block
__device__ unsigned int g_ctr;            // completion counter, self-resetting

// ======================= pass 1: max + sampled histogram ====================
__device__ __forceinline__ float q4max(float4 v) {
    return fmaxf(fmaxf(fabsf(v.x), fabsf(v.y)), fmaxf(fabsf(v.z), fabsf(v.w)));
}

__global__ void hq_pass1(const float4* __restrict__ x, long long n4,
                         const float* __restrict__ xs, long long n) {
    __shared__ unsigned int sh[NBINS];
    for (int i = threadIdx.x; i < NBINS; i += blockDim.x) sh[i] = 0u;
    __syncthreads();

    float mymax = 0.0f;
    // fold scalar tail (n % 4) into the max (block 0, thread 0)
    if (blockIdx.x == 0 && threadIdx.x == 0) {
        for (long long j = n4 * 4; j < n; j++) mymax = fmaxf(mymax, fabsf(xs[j]));
    }

    const long long stride = (long long)gridDim.x * blockDim.x; // multiple of 8
    long long i = (long long)blockIdx.x * blockDim.x + threadIdx.x;

    for (; i + 3 * stride < n4; i += 4 * stride) {
        // default caching: leave x resident in L2 for the quant pass
        float4 v0 = x[i];
        float4 v1 = x[i + stride];
        float4 v2 = x[i + 2 * stride];
        float4 v3 = x[i + 3 * stride];
        mymax = fmaxf(mymax, fmaxf(fmaxf(q4max(v0), q4max(v1)),
                                   fmaxf(q4max(v2), q4max(v3))));
        if ((i & 7) == 0) {   // 1/32 sample; predicate shared by all 4 (stride%8==0)
            atomicAdd(&sh[(__float_as_uint(v0.x) & 0x7fffffffu) >> 19], 1u);
            atomicAdd(&sh[(__float_as_uint(v1.x) & 0x7fffffffu) >> 19], 1u);
            atomicAdd(&sh[(__float_as_uint(v2.x) & 0x7fffffffu) >> 19], 1u);
            atomicAdd(&sh[(__float_as_uint(v3.x) & 0x7fffffffu) >> 19], 1u);
        }
    }
    for (; i < n4; i += stride) {
        float4 v = x[i];
        mymax = fmaxf(mymax, q4max(v));
        if ((i & 7) == 0)
            atomicAdd(&sh[(__float_as_uint(v.x) & 0x7fffffffu) >> 19], 1u);
    }
    __syncthreads();

    for (int b = threadIdx.x; b < NBINS; b += blockDim.x) {
        unsigned c = sh[b];
        if (c) atomicAdd(&g_hist[b], c);
    }

    #pragma unroll
    for (int o = 16; o; o >>= 1)
        mymax = fmaxf(mymax, __shfl_xor_sync(0xffffffffu, mymax, o));
    __shared__ float wmax[P1_THREADS / 32];
    if ((threadIdx.x & 31) == 0) wmax[threadIdx.x >> 5] = mymax;
    __syncthreads();
    if (threadIdx.x == 0) {
        float m = 0.0f;
        #pragma unroll
        for (int w = 0; w < P1_THREADS / 32; w++) m = fmaxf(m, wmax[w]);
        atomicMax(&g_maxbits, __float_as_uint(m)); // non-neg: uint order == float order
    }
}

// ======================= quant (+ scan in block 0) ==========================
__device__ __forceinline__ float4 quant4(float4 v, float s, float inv) {
    float4 o;
    o.x = fminf(127.0f, fmaxf(-127.0f, rintf(v.x * s))) * inv;
    o.y = fminf(127.0f, fmaxf(-127.0f, rintf(v.y * s))) * inv;
    o.z = fminf(127.0f, fmaxf(-127.0f, rintf(v.z * s))) * inv;
    o.w = fminf(127.0f, fmaxf(-127.0f, rintf(v.w * s))) * inv;
    return o;
}

__global__ void __launch_bounds__(Q_THREADS)
hq_quant(const float4* __restrict__ x, float4* __restrict__ out,
         long long n4, const float* __restrict__ xs, float* __restrict__ outs,
         long long n, long long out_size, long long ksel) {
    const unsigned mb = g_maxbits;
    const float maxv = __uint_as_float(mb);
    const float s = 127.0f / maxv;       // EPS = 0
    const float inv = 1.0f / s;

    // ---- block 0: parallel percentile scan + buffer write + hist re-zero ----
    if (blockIdx.x == 0) {
        __shared__ unsigned int sh[NBINS];
        __shared__ int s_chunk;
        __shared__ unsigned int s_cum;
        const int t = threadIdx.x;

        unsigned csum = 0;
        #pragma unroll
        for (int j = 0; j < NBINS / 256; j++) {
            unsigned c = g_hist[t * (NBINS / 256) + j];
            sh[t * (NBINS / 256) + j] = c;
            g_hist[t * (NBINS / 256) + j] = 0u;   // clean for next replay
            csum += c;
        }

        // block-wide exclusive scan of csum (warp shuffles + warp sums)
        unsigned v = csum;
        #pragma unroll
        for (int o = 1; o < 32; o <<= 1) {
            unsigned u = __shfl_up_sync(0xffffffffu, v, o);
            if ((t & 31) >= o) v += u;
        }                                          // v = inclusive within warp
        __shared__ unsigned int wsum[8];
        if ((t & 31) == 31) wsum[t >> 5] = v;
        __syncthreads();
        if (t < 8) {
            unsigned w = wsum[t];
            #pragma unroll
            for (int o = 1; o < 8; o <<= 1) {
                unsigned u = __shfl_up_sync(0xffu, w, o);
                if (t >= o) w += u;
            }
            wsum[t] = w;                           // inclusive warp sums
        }
        __syncthreads();
        unsigned excl = v - csum + ((t >> 5) ? wsum[(t >> 5) - 1] : 0u);
        // locate winning chunk: excl < ksel <= excl + csum  (exactly one t)
        if ((unsigned long long)excl < (unsigned long long)ksel &&
            (unsigned long long)(excl + csum) >= (unsigned long long)ksel) {
            s_chunk = t;
            s_cum = excl;
        }
        __syncthreads();

        if (t == 0) {
            int chunk = s_chunk;
            unsigned long long cum = s_cum;
            int b = chunk * (NBINS / 256);
            unsigned cnt = 0;
            #pragma unroll
            for (int j = 0; j < NBINS / 256; j++) {
                int idx = chunk * (NBINS / 256) + j;
                unsigned c = sh[idx];
                if (cum + c >= (unsigned long long)ksel) { b = idx; cnt = c; break; }
                cum += c;
            }
            float clampv;
            if (cnt == 0u) {
                clampv = maxv;
            } else {
                float lo = __uint_as_float((unsigned)b << 19);
                float hi = __uint_as_float((unsigned)(b + 1) << 19);
                double frac = (double)((long long)ksel - (long long)cum) / (double)cnt;
                clampv = lo + (hi - lo) * (float)frac;
            }
            float buf = 100.0f * 0.99f + clampv * (1.0f - 0.99f);
            if (out_size > n) outs[n] = buf;
        }
        __syncthreads();
    }

    // ---- streaming quantization, REVERSED order (consume L2-hot tail) ----
    const long long stride = (long long)gridDim.x * blockDim.x;
    long long idx = (long long)blockIdx.x * blockDim.x + threadIdx.x;

    for (; idx + 3 * stride < n4; idx += 4 * stride) {
        const long long i0 = n4 - 1 - idx;
        const long long i1 = i0 - stride;
        const long long i2 = i0 - 2 * stride;
        const long long i3 = i0 - 3 * stride;
        float4 v0 = x[i0];          // default policy: harvest L2 hits
        float4 v1 = x[i1];
        float4 v2 = x[i2];
        float4 v3 = x[i3];
        __stcs(&out[i0], quant4(v0, s, inv));   // evict-first stores
        __stcs(&out[i1], quant4(v1, s, inv));
        __stcs(&out[i2], quant4(v2, s, inv));
        __stcs(&out[i3], quant4(v3, s, inv));
    }
    for (; idx < n4; idx += stride) {
        const long long i0 = n4 - 1 - idx;
        __stcs(&out[i0], quant4(x[i0], s, inv));
    }

    // scalar tail (n % 4)
    long long gtid = (long long)blockIdx.x * blockDim.x + threadIdx.x;
    long long tail = n - n4 * 4;
    if (gtid < tail)
        outs[n4 * 4 + gtid] =
            fminf(127.0f, fmaxf(-127.0f, rintf(xs[n4 * 4 + gtid] * s))) * inv;

    // ---- self-cleaning device state (last block resets) ----
    __syncthreads();
    if (threadIdx.x == 0) {
        unsigned done = atomicAdd(&g_ctr, 1u);
        if (done == gridDim.x - 1) {
            g_maxbits = 0u;
            g_ctr = 0u;
        }
    }
}

// ---------------------------------------------------------------------------
extern "C" void kernel_launch(void* const* d_in, const int* in_sizes, int n_in,
                              void* d_out, int out_size) {
    const float* x = (const float*)d_in[0];
    float* out = (float*)d_out;
    const long long n = (long long)in_sizes[0];
    const long long n4 = n / 4;

    // sampled set: quads with index % 8 == 0
    const long long ns = (n4 + 7) / 8;
    long long ksel = (long long)llround((99.99 / 100.0) * (double)ns);
    if (ksel < 1) ksel = 1;
    if (ksel > ns) ksel = ns;

    long long p1_blocks = (n4 + P1_THREADS - 1) / P1_THREADS;
    if (p1_blocks > P1_BLOCKS) p1_blocks = P1_BLOCKS;
    if (p1_blocks < 1) p1_blocks = 1;
    hq_pass1<<<(int)p1_blocks, P1_THREADS>>>((const float4*)x, n4, x, n);

    long long qb = (n4 + Q_THREADS - 1) / Q_THREADS;
    if (qb > Q_BLOCKS) qb = Q_BLOCKS;
    if (qb < 1) qb = 1;
    hq_quant<<<(int)qb, Q_THREADS>>>((const float4*)x, (float4*)out, n4,
                                     x, out, n, (long long)out_size, ksel);
}

// round 7
// speedup vs baseline: 1.0153x; 1.0153x over previous
#include <cuda_runtime.h>
#include <stdint.h>

// ---------------------------------------------------------------------------
// HistogramQuantizer R7 — TMA (cp.async.bulk) pipelines, LSU-issue-free:
//   pass1: 3-stage 8KB TMA g->s pipeline; max|x| via LDS.128 + FMNMX;
//          sampled histogram (1/32) in shared; tails via plain loads (block 0).
//   quant: block 0 does percentile scan (scratch = out-tiles) overlapped with
//          its initial TMA issues; all blocks: TMA in -> quant in regs ->
//          STS -> TMA bulk store out (2 out stages, bulk_group backpressure).
//   Sampling set, histogram, max, and quant arithmetic identical to R4.
// ---------------------------------------------------------------------------

#define NBINS   4096
#define THREADS 256
#define T_F4    512        // float4 per tile  (8 KB)
#define T_BYTES 8192
#define P_S     3          // input pipeline stages
#define QO      2          // output store stages
#define GRID    740        // 148 SMs * 5 (40KB smem -> 5 blocks/SM)

__device__ unsigned int g_hist[NBINS];   // zero at load; scan re-zeroes each run
__device__ unsigned int g_maxbits;       // reset by last quant block
__device__ unsigned int g_ctr;           // completion counter, self-resetting

// ======================= PTX helpers =======================================
static __device__ __forceinline__ uint32_t sm32(const void* p) {
    uint32_t a;
    asm("{ .reg .u64 t; cvta.to.shared.u64 t, %1; cvt.u32.u64 %0, t; }"
        : "=r"(a) : "l"(p));
    return a;
}
static __device__ __forceinline__ void mbar_init(uint32_t m, uint32_t c) {
    asm volatile("mbarrier.init.shared.b64 [%0], %1;" :: "r"(m), "r"(c) : "memory");
}
static __device__ __forceinline__ void mbar_expect(uint32_t m, uint32_t bytes) {
    asm volatile("mbarrier.arrive.expect_tx.shared.b64 _, [%0], %1;"
                 :: "r"(m), "r"(bytes) : "memory");
}
static __device__ __forceinline__ void mbar_wait(uint32_t m, uint32_t parity) {
    asm volatile(
        "{\n\t.reg .pred P;\n"
        "LW%=:\n\t"
        "mbarrier.try_wait.parity.acquire.cta.shared::cta.b64 P, [%0], %1, 0x989680;\n\t"
        "@P bra LD%=;\n\t"
        "bra LW%=;\n"
        "LD%=:\n\t}"
        :: "r"(m), "r"(parity) : "memory");
}
static __device__ __forceinline__ void g2s(uint32_t dst, const void* src,
                                           uint32_t bytes, uint32_t m) {
    asm volatile(
        "cp.async.bulk.shared::cta.global.mbarrier::complete_tx::bytes [%0], [%1], %2, [%3];"
        :: "r"(dst), "l"(src), "r"(bytes), "r"(m) : "memory");
}
static __device__ __forceinline__ void s2g(void* dst, uint32_t src, uint32_t bytes) {
    asm volatile("cp.async.bulk.global.shared::cta.bulk_group [%0], [%1], %2;"
                 :: "l"(dst), "r"(src), "r"(bytes) : "memory");
}
#define BULK_COMMIT() asm volatile("cp.async.bulk.commit_group;" ::: "memory")
template <int N>
static __device__ __forceinline__ void bulk_wait_group() {
    asm volatile("cp.async.bulk.wait_group %0;" :: "n"(N) : "memory");
}
#define FENCE_ASYNC() asm volatile("fence.proxy.async.shared::cta;" ::: "memory")

// ======================= pass 1: max + sampled histogram ====================
__device__ __forceinline__ float q4max(float4 v) {
    return fmaxf(fmaxf(fabsf(v.x), fabsf(v.y)), fmaxf(fabsf(v.z), fabsf(v.w)));
}

__global__ void __launch_bounds__(THREADS)
hq_pass1(const float4* __restrict__ x, long long n4,
         const float* __restrict__ xs, long long n, long long nt) {
    __shared__ float4 tiles[P_S][T_F4];           // 24 KB
    __shared__ unsigned int hist[NBINS];          // 16 KB
    __shared__ unsigned long long mbar[P_S];
    __shared__ float wmax[THREADS / 32];

    const int tid = threadIdx.x;
    const uint32_t mb0 = sm32(&mbar[0]);

    for (int i = tid; i < NBINS; i += THREADS) hist[i] = 0u;
    if (tid == 0)
        for (int s = 0; s < P_S; s++) mbar_init(mb0 + 8u * s, 1u);
    __syncthreads();

    // initial TMA issues (stages 0..P_S-1)
    if (tid == 0) {
        long long ti = blockIdx.x;
        for (int s = 0; s < P_S && ti < nt; s++, ti += gridDim.x) {
            mbar_expect(mb0 + 8u * s, T_BYTES);
            g2s(sm32(&tiles[s][0]), (const void*)(x + ti * T_F4), T_BYTES,
                mb0 + 8u * s);
        }
    }

    float mymax = 0.0f;
    // tails (block 0): remainder quads + scalar tail, same sampling rule
    if (blockIdx.x == 0) {
        for (long long q = nt * T_F4 + tid; q < n4; q += THREADS) {
            float4 v = x[q];
            mymax = fmaxf(mymax, q4max(v));
            if ((q & 7) == 0)
                atomicAdd(&hist[(__float_as_uint(v.x) & 0x7fffffffu) >> 19], 1u);
        }
        if (tid == 0)
            for (long long j = n4 * 4; j < n; j++)
                mymax = fmaxf(mymax, fabsf(xs[j]));
    }

    int slot = 0, phase = 0;
    for (long long t = blockIdx.x; t < nt; t += gridDim.x) {
        mbar_wait(mb0 + 8u * slot, (uint32_t)phase);
        float4 v0 = tiles[slot][tid];
        float4 v1 = tiles[slot][tid + THREADS];
        mymax = fmaxf(mymax, fmaxf(q4max(v0), q4max(v1)));
        // global quad = t*512 + q, 512%8==0 -> sample iff (tid%8)==0 (both q's)
        if ((tid & 7) == 0) {
            atomicAdd(&hist[(__float_as_uint(v0.x) & 0x7fffffffu) >> 19], 1u);
            atomicAdd(&hist[(__float_as_uint(v1.x) & 0x7fffffffu) >> 19], 1u);
        }
        __syncthreads();   // tile fully consumed -> safe to re-arm
        if (tid == 0) {
            long long tn = t + (long long)P_S * gridDim.x;
            if (tn < nt) {
                mbar_expect(mb0 + 8u * slot, T_BYTES);
                g2s(sm32(&tiles[slot][0]), (const void*)(x + tn * T_F4),
                    T_BYTES, mb0 + 8u * slot);
            }
        }
        if (++slot == P_S) { slot = 0; phase ^= 1; }
    }
    __syncthreads();

    // flush nonzero bins
    for (int b = tid; b < NBINS; b += THREADS) {
        unsigned c = hist[b];
        if (c) atomicAdd(&g_hist[b], c);
    }

    // block max reduction -> one atomicMax per block
    #pragma unroll
    for (int o = 16; o; o >>= 1)
        mymax = fmaxf(mymax, __shfl_xor_sync(0xffffffffu, mymax, o));
    if ((tid & 31) == 0) wmax[tid >> 5] = mymax;
    __syncthreads();
    if (tid == 0) {
        float m = 0.0f;
        #pragma unroll
        for (int w = 0; w < THREADS / 32; w++) m = fmaxf(m, wmax[w]);
        atomicMax(&g_maxbits, __float_as_uint(m)); // non-neg: uint order == float
    }
}

// ======================= quant (+ scan in block 0) ==========================
__device__ __forceinline__ float4 quant4(float4 v, float s, float inv) {
    float4 o;
    o.x = fminf(127.0f, fmaxf(-127.0f, rintf(v.x * s))) * inv;
    o.y = fminf(127.0f, fmaxf(-127.0f, rintf(v.y * s))) * inv;
    o.z = fminf(127.0f, fmaxf(-127.0f, rintf(v.z * s))) * inv;
    o.w = fminf(127.0f, fmaxf(-127.0f, rintf(v.w * s))) * inv;
    return o;
}

__global__ void __launch_bounds__(THREADS)
hq_quant(const float4* __restrict__ x, float4* __restrict__ out, long long n4,
         const float* __restrict__ xs, float* __restrict__ outs,
         long long n, long long out_size, long long ksel, long long nt) {
    __shared__ float4 tiles[P_S][T_F4];           // 24 KB
    __shared__ float4 otile[QO][T_F4];            // 16 KB (scan scratch too)
    __shared__ unsigned long long mbar[P_S];
    __shared__ unsigned int wsum[THREADS / 32];
    __shared__ int s_chunk;
    __shared__ unsigned int s_cum;

    const int tid = threadIdx.x;
    const uint32_t mb0 = sm32(&mbar[0]);

    const unsigned mbv = g_maxbits;
    const float maxv = __uint_as_float(mbv);
    const float s = 127.0f / maxv;      // EPS = 0
    const float inv = 1.0f / s;

    if (tid == 0)
        for (int st = 0; st < P_S; st++) mbar_init(mb0 + 8u * st, 1u);
    __syncthreads();

    // initial TMA issues (overlap with block 0's scan below)
    if (tid == 0) {
        long long ti = blockIdx.x;
        for (int st = 0; st < P_S && ti < nt; st++, ti += gridDim.x) {
            mbar_expect(mb0 + 8u * st, T_BYTES);
            g2s(sm32(&tiles[st][0]), (const void*)(x + ti * T_F4), T_BYTES,
                mb0 + 8u * st);
        }
    }

    // ---- block 0: parallel percentile scan (scratch = otile) --------------
    if (blockIdx.x == 0) {
        unsigned int* sh = (unsigned int*)&otile[0][0];   // 4096 uints = 16 KB
        unsigned csum = 0;
        #pragma unroll
        for (int j = 0; j < NBINS / THREADS; j++) {
            int idx = tid * (NBINS / THREADS) + j;
            unsigned c = g_hist[idx];
            sh[idx] = c;
            g_hist[idx] = 0u;                 // clean for next graph replay
            csum += c;
        }
        unsigned v = csum;
        #pragma unroll
        for (int o = 1; o < 32; o <<= 1) {
            unsigned u = __shfl_up_sync(0xffffffffu, v, o);
            if ((tid & 31) >= o) v += u;
        }
        if ((tid & 31) == 31) wsum[tid >> 5] = v;
        __syncthreads();
        if (tid < THREADS / 32) {
            unsigned w = wsum[tid];
            #pragma unroll
            for (int o = 1; o < THREADS / 32; o <<= 1) {
                unsigned u = __shfl_up_sync((1u << (THREADS / 32)) - 1u, w, o);
                if (tid >= o) w += u;
            }
            wsum[tid] = w;
        }
        __syncthreads();
        unsigned excl = v - csum + ((tid >> 5) ? wsum[(tid >> 5) - 1] : 0u);
        if ((unsigned long long)excl < (unsigned long long)ksel &&
            (unsigned long long)(excl + csum) >= (unsigned long long)ksel) {
            s_chunk = tid;
            s_cum = excl;
        }
        __syncthreads();
        if (tid == 0) {
            int chunk = s_chunk;
            unsigned long long cum = s_cum;
            int b = chunk * (NBINS / THREADS);
            unsigned cnt = 0;
            #pragma unroll
            for (int j = 0; j < NBINS / THREADS; j++) {
                int idx = chunk * (NBINS / THREADS) + j;
                unsigned c = sh[idx];
                if (cum + c >= (unsigned long long)ksel) { b = idx; cnt = c; break; }
                cum += c;
            }
            float clampv;
            if (cnt == 0u) {
                clampv = maxv;
            } else {
                float lo = __uint_as_float((unsigned)b << 19);
                float hi = __uint_as_float((unsigned)(b + 1) << 19);
                double frac =
                    (double)((long long)ksel - (long long)cum) / (double)cnt;
                clampv = lo + (hi - lo) * (float)frac;
            }
            float buf = 100.0f * 0.99f + clampv * (1.0f - 0.99f);
            if (out_size > n) outs[n] = buf;
        }
        __syncthreads();

        // tails: remainder quads + scalar tail (plain loads, tiny)
        for (long long q = nt * T_F4 + tid; q < n4; q += THREADS)
            out[q] = quant4(x[q], s, inv);
        for (long long j = n4 * 4 + tid; j < n; j += THREADS)
            outs[j] = fminf(127.0f, fmaxf(-127.0f, rintf(xs[j] * s))) * inv;
    }

    // ---- TMA-pipelined streaming quantization ------------------------------
    int slot = 0, phase = 0, os = 0;
    long long k = 0;
    for (long long t = blockIdx.x; t < nt; t += gridDim.x, k++) {
        mbar_wait(mb0 + 8u * slot, (uint32_t)phase);
        if (k >= QO) {
            if (tid == 0) bulk_wait_group<QO - 1>();  // out-stage os free
        }
        __syncthreads();

        float4 v0 = tiles[slot][tid];
        float4 v1 = tiles[slot][tid + THREADS];
        otile[os][tid]           = quant4(v0, s, inv);
        otile[os][tid + THREADS] = quant4(v1, s, inv);
        __syncthreads();   // out tile complete, in tile fully consumed

        if (tid == 0) {
            long long tn = t + (long long)P_S * gridDim.x;
            if (tn < nt) {
                mbar_expect(mb0 + 8u * slot, T_BYTES);
                g2s(sm32(&tiles[slot][0]), (const void*)(x + tn * T_F4),
                    T_BYTES, mb0 + 8u * slot);
            }
            FENCE_ASYNC();
            s2g((void*)(out + t * T_F4), sm32(&otile[os][0]), T_BYTES);
            BULK_COMMIT();
        }
        if (++slot == P_S) { slot = 0; phase ^= 1; }
        if (++os == QO) os = 0;
    }
    if (tid == 0) bulk_wait_group<0>();   // drain stores before exit

    // ---- self-cleaning device state (last block resets) --------------------
    __syncthreads();
    if (tid == 0) {
        unsigned done = atomicAdd(&g_ctr, 1u);
        if (done == gridDim.x - 1) {
            g_maxbits = 0u;
            g_ctr = 0u;
        }
    }
}

// ---------------------------------------------------------------------------
extern "C" void kernel_launch(void* const* d_in, const int* in_sizes, int n_in,
                              void* d_out, int out_size) {
    const float* x = (const float*)d_in[0];
    float* out = (float*)d_out;
    const long long n = (long long)in_sizes[0];
    const long long n4 = n / 4;
    const long long nt = n4 / T_F4;            // full 8KB tiles

    // sampled set: quads with index % 8 == 0
    const long long ns = (n4 + 7) / 8;
    long long ksel = (long long)llround((99.99 / 100.0) * (double)ns);
    if (ksel < 1) ksel = 1;
    if (ksel > ns) ksel = ns;

    long long g = nt;
    if (g > GRID) g = GRID;
    if (g < 1) g = 1;

    hq_pass1<<<(int)g, THREADS>>>((const float4*)x, n4, x, n, nt);
    hq_quant<<<(int)g, THREADS>>>((const float4*)x, (float4*)out, n4,
                                  x, out, n, (long long)out_size, ksel, nt);
}

// round 8
// speedup vs baseline: 1.0314x; 1.0158x over previous
#include <cuda_runtime.h>
#include <stdint.h>

// ---------------------------------------------------------------------------
// HistogramQuantizer R8 — R5's proven LDG engines + PDL overlap:
//   pass1: stream x (unroll x4, __ldcs, MLP=4) -> exact max|x| (FMNMX tree,
//          at the 1-op/elem fma+alu floor) + 4096-bin sampled histogram
//          (1/32, shared-privatized). Triggers programmatic launch completion
//          right after its streaming loop so quant's blocks start early.
//   quant: PDL dependent. Prefetches its first 4 float4 of x (input-only,
//          safe pre-sync), then cudaGridDependencySynchronize(), then block 0
//          runs the parallel percentile scan (EMA buffer -> d_out[n], re-zeroes
//          g_hist) while all blocks stream x->out (unroll x4, __ldcs/__stcs).
//          Last block self-cleans g_maxbits/g_ctr (deterministic replays).
// ---------------------------------------------------------------------------

#define NBINS 4096
#define P1_THREADS 256
#define P1_BLOCKS 1184   // 148 SMs * 8 ; stride multiple of 8
#define Q_THREADS 256
#define Q_BLOCKS 2368    // 148 SMs * 16

__device__ unsigned int g_hist[NBINS];    // zero at module load; scan re-zeroes
__device__ unsigned int g_maxbits;        // reset by last quant block
__device__ unsigned int g_ctr;            // completion counter, self-resetting

// ======================= pass 1: max + sampled histogram ====================
__device__ __forceinline__ float q4max(float4 v) {
    return fmaxf(fmaxf(fabsf(v.x), fabsf(v.y)), fmaxf(fabsf(v.z), fabsf(v.w)));
}

__global__ void __launch_bounds__(P1_THREADS)
hq_pass1(const float4* __restrict__ x, long long n4,
         const float* __restrict__ xs, long long n) {
    __shared__ unsigned int sh[NBINS];
    for (int i = threadIdx.x; i < NBINS; i += blockDim.x) sh[i] = 0u;
    __syncthreads();

    float mymax = 0.0f;
    // fold scalar tail (n % 4) into the max (block 0, thread 0)
    if (blockIdx.x == 0 && threadIdx.x == 0) {
        for (long long j = n4 * 4; j < n; j++) mymax = fmaxf(mymax, fabsf(xs[j]));
    }

    const long long stride = (long long)gridDim.x * blockDim.x; // multiple of 8
    long long i = (long long)blockIdx.x * blockDim.x + threadIdx.x;

    for (; i + 3 * stride < n4; i += 4 * stride) {
        float4 v0 = __ldcs(&x[i]);
        float4 v1 = __ldcs(&x[i + stride]);
        float4 v2 = __ldcs(&x[i + 2 * stride]);
        float4 v3 = __ldcs(&x[i + 3 * stride]);
        mymax = fmaxf(mymax, fmaxf(fmaxf(q4max(v0), q4max(v1)),
                                   fmaxf(q4max(v2), q4max(v3))));
        if ((i & 7) == 0) {   // 1/32 sample; predicate shared by all 4 (stride%8==0)
            atomicAdd(&sh[(__float_as_uint(v0.x) & 0x7fffffffu) >> 19], 1u);
            atomicAdd(&sh[(__float_as_uint(v1.x) & 0x7fffffffu) >> 19], 1u);
            atomicAdd(&sh[(__float_as_uint(v2.x) & 0x7fffffffu) >> 19], 1u);
            atomicAdd(&sh[(__float_as_uint(v3.x) & 0x7fffffffu) >> 19], 1u);
        }
    }
    for (; i < n4; i += stride) {
        float4 v = __ldcs(&x[i]);
        mymax = fmaxf(mymax, q4max(v));
        if ((i & 7) == 0)
            atomicAdd(&sh[(__float_as_uint(v.x) & 0x7fffffffu) >> 19], 1u);
    }

    // streaming done -> let dependent grid start launching (its pre-sync
    // work only reads x, which this kernel never writes)
    cudaTriggerProgrammaticLaunchCompletion();
    __syncthreads();

    for (int b = threadIdx.x; b < NBINS; b += blockDim.x) {
        unsigned c = sh[b];
        if (c) atomicAdd(&g_hist[b], c);
    }

    #pragma unroll
    for (int o = 16; o; o >>= 1)
        mymax = fmaxf(mymax, __shfl_xor_sync(0xffffffffu, mymax, o));
    __shared__ float wmax[P1_THREADS / 32];
    if ((threadIdx.x & 31) == 0) wmax[threadIdx.x >> 5] = mymax;
    __syncthreads();
    if (threadIdx.x == 0) {
        float m = 0.0f;
        #pragma unroll
        for (int w = 0; w < P1_THREADS / 32; w++) m = fmaxf(m, wmax[w]);
        atomicMax(&g_maxbits, __float_as_uint(m)); // non-neg: uint order == float
    }
}

// ======================= quant (+ scan in block 0) ==========================
__device__ __forceinline__ float4 quant4(float4 v, float s, float inv) {
    float4 o;
    o.x = fminf(127.0f, fmaxf(-127.0f, rintf(v.x * s))) * inv;
    o.y = fminf(127.0f, fmaxf(-127.0f, rintf(v.y * s))) * inv;
    o.z = fminf(127.0f, fmaxf(-127.0f, rintf(v.z * s))) * inv;
    o.w = fminf(127.0f, fmaxf(-127.0f, rintf(v.w * s))) * inv;
    return o;
}

__global__ void __launch_bounds__(Q_THREADS)
hq_quant(const float4* __restrict__ x, float4* __restrict__ out,
         long long n4, const float* __restrict__ xs, float* __restrict__ outs,
         long long n, long long out_size, long long ksel) {
    const long long stride = (long long)gridDim.x * blockDim.x;
    const long long i0 = (long long)blockIdx.x * blockDim.x + threadIdx.x;

    // ---- pre-sync prefetch: x is input-only, safe before primary completes --
    float4 p0, p1, p2, p3;
    const bool pf4 = (i0 + 3 * stride < n4);
    const bool pf1 = (i0 < n4);
    if (pf4) {
        p0 = __ldcs(&x[i0]);
        p1 = __ldcs(&x[i0 + stride]);
        p2 = __ldcs(&x[i0 + 2 * stride]);
        p3 = __ldcs(&x[i0 + 3 * stride]);
    } else if (pf1) {
        p0 = __ldcs(&x[i0]);
    }

    cudaGridDependencySynchronize();   // pass1 fully complete + visible

    const unsigned mb = g_maxbits;
    const float maxv = __uint_as_float(mb);
    const float s = 127.0f / maxv;       // EPS = 0
    const float inv = 1.0f / s;

    // ---- block 0: parallel percentile scan + buffer write + hist re-zero ----
    if (blockIdx.x == 0) {
        __shared__ unsigned int sh[NBINS];
        __shared__ int s_chunk;
        __shared__ unsigned int s_cum;
        const int t = threadIdx.x;

        unsigned csum = 0;
        #pragma unroll
        for (int j = 0; j < NBINS / 256; j++) {
            unsigned c = g_hist[t * (NBINS / 256) + j];
            sh[t * (NBINS / 256) + j] = c;
            g_hist[t * (NBINS / 256) + j] = 0u;   // clean for next replay
            csum += c;
        }

        // block-wide exclusive scan of csum (warp shuffles + warp sums)
        unsigned v = csum;
        #pragma unroll
        for (int o = 1; o < 32; o <<= 1) {
            unsigned u = __shfl_up_sync(0xffffffffu, v, o);
            if ((t & 31) >= o) v += u;
        }                                          // inclusive within warp
        __shared__ unsigned int wsum[8];
        if ((t & 31) == 31) wsum[t >> 5] = v;
        __syncthreads();
        if (t < 8) {
            unsigned w = wsum[t];
            #pragma unroll
            for (int o = 1; o < 8; o <<= 1) {
                unsigned u = __shfl_up_sync(0xffu, w, o);
                if (t >= o) w += u;
            }
            wsum[t] = w;                           // inclusive warp sums
        }
        __syncthreads();
        unsigned excl = v - csum + ((t >> 5) ? wsum[(t >> 5) - 1] : 0u);
        // winning chunk: excl < ksel <= excl + csum (exactly one t)
        if ((unsigned long long)excl < (unsigned long long)ksel &&
            (unsigned long long)(excl + csum) >= (unsigned long long)ksel) {
            s_chunk = t;
            s_cum = excl;
        }
        __syncthreads();

        if (t == 0) {
            int chunk = s_chunk;
            unsigned long long cum = s_cum;
            int b = chunk * (NBINS / 256);
            unsigned cnt = 0;
            #pragma unroll
            for (int j = 0; j < NBINS / 256; j++) {
                int idx = chunk * (NBINS / 256) + j;
                unsigned c = sh[idx];
                if (cum + c >= (unsigned long long)ksel) { b = idx; cnt = c; break; }
                cum += c;
            }
            float clampv;
            if (cnt == 0u) {
                clampv = maxv;
            } else {
                float lo = __uint_as_float((unsigned)b << 19);
                float hi = __uint_as_float((unsigned)(b + 1) << 19);
                double frac =
                    (double)((long long)ksel - (long long)cum) / (double)cnt;
                clampv = lo + (hi - lo) * (float)frac;
            }
            float buf = 100.0f * 0.99f + clampv * (1.0f - 0.99f);
            if (out_size > n) outs[n] = buf;
        }
        __syncthreads();
    }

    // ---- streaming quantization (prefetched first batch, then loop) --------
    long long i = i0;
    if (pf4) {
        __stcs(&out[i],              quant4(p0, s, inv));
        __stcs(&out[i + stride],     quant4(p1, s, inv));
        __stcs(&out[i + 2 * stride], quant4(p2, s, inv));
        __stcs(&out[i + 3 * stride], quant4(p3, s, inv));
        i += 4 * stride;
    } else if (pf1) {
        __stcs(&out[i], quant4(p0, s, inv));
        i += stride;
    }

    for (; i + 3 * stride < n4; i += 4 * stride) {
        float4 v0 = __ldcs(&x[i]);
        float4 v1 = __ldcs(&x[i + stride]);
        float4 v2 = __ldcs(&x[i + 2 * stride]);
        float4 v3 = __ldcs(&x[i + 3 * stride]);
        __stcs(&out[i],              quant4(v0, s, inv));
        __stcs(&out[i + stride],     quant4(v1, s, inv));
        __stcs(&out[i + 2 * stride], quant4(v2, s, inv));
        __stcs(&out[i + 3 * stride], quant4(v3, s, inv));
    }
    for (; i < n4; i += stride)
        __stcs(&out[i], quant4(__ldcs(&x[i]), s, inv));

    // scalar tail (n % 4)
    long long gtid = i0;
    long long tail = n - n4 * 4;
    if (gtid < tail)
        outs[n4 * 4 + gtid] =
            fminf(127.0f, fmaxf(-127.0f, rintf(xs[n4 * 4 + gtid] * s))) * inv;

    // ---- self-cleaning device state (last block resets) --------------------
    __syncthreads();
    if (threadIdx.x == 0) {
        unsigned done = atomicAdd(&g_ctr, 1u);
        if (done == gridDim.x - 1) {
            g_maxbits = 0u;
            g_ctr = 0u;
        }
    }
}

// ---------------------------------------------------------------------------
extern "C" void kernel_launch(void* const* d_in, const int* in_sizes, int n_in,
                              void* d_out, int out_size) {
    const float* x = (const float*)d_in[0];
    float* out = (float*)d_out;
    const long long n = (long long)in_sizes[0];
    const long long n4 = n / 4;

    // sampled set: quads with index % 8 == 0
    const long long ns = (n4 + 7) / 8;
    long long ksel = (long long)llround((99.99 / 100.0) * (double)ns);
    if (ksel < 1) ksel = 1;
    if (ksel > ns) ksel = ns;

    long long p1_blocks = (n4 + P1_THREADS - 1) / P1_THREADS;
    if (p1_blocks > P1_BLOCKS) p1_blocks = P1_BLOCKS;
    if (p1_blocks < 1) p1_blocks = 1;
    hq_pass1<<<(int)p1_blocks, P1_THREADS>>>((const float4*)x, n4, x, n);

    long long qb = (n4 + Q_THREADS - 1) / Q_THREADS;
    if (qb > Q_BLOCKS) qb = Q_BLOCKS;
    if (qb < 1) qb = 1;

    // PDL: quant's blocks may launch once pass1 triggers; the in-kernel
    // cudaGridDependencySynchronize() orders all result reads.
    cudaLaunchConfig_t cfg = {};
    cfg.gridDim = dim3((unsigned)qb, 1, 1);
    cfg.blockDim = dim3(Q_THREADS, 1, 1);
    cfg.dynamicSmemBytes = 0;
    cfg.stream = 0;
    cudaLaunchAttribute attrs[1];
    attrs[0].id = cudaLaunchAttributeProgrammaticStreamSerialization;
    attrs[0].val.programmaticStreamSerializationAllowed = 1;
    cfg.attrs = attrs;
    cfg.numAttrs = 1;

    const float4* x4 = (const float4*)x;
    float4* out4 = (float4*)out;
    long long oss = (long long)out_size;
    cudaLaunchKernelEx(&cfg, hq_quant, x4, out4, n4, x, out, n, oss, ksel);
}